// round 1
// baseline (speedup 1.0000x reference)
#include <cuda_runtime.h>
#include <cstdint>
#include <cfloat>

// Problem constants
#define NB   128
#define NP   8732
#define NC   21
#define TOPK 200

// NMS kernel config
#define NT   1024                 // threads per block (32 warps)
#define KPT  9                    // ceil(NP / NT)
#define NPAD (NT * KPT)           // 9216

// Scratch (device globals: no allocation allowed)
__device__ float         g_scores[NB * NP];
__device__ float4        g_boxes [NB * NP];
__device__ unsigned char g_cls   [NB * NP];

// ---------------------------------------------------------------------------
// Stage 1: softmax-max + class argmax + box decode, one thread per (b, p) row
// ---------------------------------------------------------------------------
__global__ void preprocess_kernel(const float* __restrict__ loc,
                                  const float* __restrict__ conf,
                                  const float* __restrict__ prior) {
    int row = blockIdx.x * blockDim.x + threadIdx.x;
    if (row >= NB * NP) return;

    const float* cp = conf + (size_t)row * NC;
    float c[NC];
#pragma unroll
    for (int i = 0; i < NC; i++) c[i] = cp[i];

    float m = c[0];
#pragma unroll
    for (int i = 1; i < NC; i++) m = fmaxf(m, c[i]);

    float sum = 0.0f;
#pragma unroll
    for (int i = 0; i < NC; i++) sum += expf(c[i] - m);

    // best non-background class (first max on ties, like jnp.argmax)
    float bm = c[1]; int bc = 1;
#pragma unroll
    for (int i = 2; i < NC; i++) {
        if (c[i] > bm) { bm = c[i]; bc = i; }
    }
    float score = expf(bm - m) / sum;
    float ms = (score > 0.01f) ? score : -1.0f;

    int p = row % NP;
    float4 l  = ((const float4*)loc)[row];
    float4 pr = ((const float4*)prior)[p];
    float cx = pr.x + l.x * 0.1f * pr.z;
    float cy = pr.y + l.y * 0.1f * pr.w;
    float w  = pr.z * expf(l.z * 0.2f);
    float h  = pr.w * expf(l.w * 0.2f);

    g_scores[row] = ms;
    g_boxes [row] = make_float4(cx - w * 0.5f, cy - h * 0.5f,
                                cx + w * 0.5f, cy + h * 0.5f);
    g_cls   [row] = (unsigned char)(bc - 1);
}

// ---------------------------------------------------------------------------
// Stage 2: per-batch sequential NMS scan (one CTA per batch).
// Scores + classes in registers (suppression is owner-local); boxes/areas/cls
// in SMEM for the broadcast of the selected box and the rare IoU computes.
// ---------------------------------------------------------------------------
#define SMEM_BYTES (NPAD * 16 + NPAD * 4 + NPAD + 33 * 4 + 33 * 4 + 16)

__global__ __launch_bounds__(NT, 1)
void nms_kernel(float* __restrict__ out) {
    extern __shared__ unsigned char smem_raw[];
    float4*        sbox  = (float4*)smem_raw;                 // NPAD float4
    float*         sarea = (float*)(sbox + NPAD);             // NPAD floats
    unsigned char* scls  = (unsigned char*)(sarea + NPAD);    // NPAD bytes
    float*         redv  = (float*)(scls + NPAD);             // 33 floats
    int*           redi  = (int*)(redv + 33);                 // 33 ints

    const int b   = blockIdx.x;
    const int tid = threadIdx.x;
    const size_t base = (size_t)b * NP;

    float s[KPT];
    unsigned char myc[KPT];

#pragma unroll
    for (int k = 0; k < KPT; k++) {
        int e = k * NT + tid;
        if (e < NP) {
            float4 bx = g_boxes[base + e];
            sbox[e]  = bx;
            sarea[e] = (bx.z - bx.x) * (bx.w - bx.y);
            unsigned char cc = g_cls[base + e];
            scls[e] = cc;
            myc[k]  = cc;
            s[k]    = g_scores[base + e];
        } else {
            myc[k] = 0xFF;      // never matches a real class (0..19)
            s[k]   = -FLT_MAX;  // never selected
        }
    }
    // packed class bytes for fast same-class filtering (pad with 0xFF)
    unsigned int p0 = (unsigned int)myc[0] | ((unsigned int)myc[1] << 8) |
                      ((unsigned int)myc[2] << 16) | ((unsigned int)myc[3] << 24);
    unsigned int p1 = (unsigned int)myc[4] | ((unsigned int)myc[5] << 8) |
                      ((unsigned int)myc[6] << 16) | ((unsigned int)myc[7] << 24);
    unsigned int p2 = (unsigned int)myc[8] | 0xFFFFFF00u;
    __syncthreads();

    float* orow = out + (size_t)b * (TOPK * 6);

    int t = 0;
    for (; t < TOPK; t++) {
        // ---- local argmax over my 9 register scores (first-index ties) ----
        float lv = s[0]; int li = tid;
#pragma unroll
        for (int k = 1; k < KPT; k++) {
            if (s[k] > lv) { lv = s[k]; li = k * NT + tid; }
        }
        // ---- warp reduce: (value desc, index asc) ----
#pragma unroll
        for (int o = 16; o > 0; o >>= 1) {
            float ov = __shfl_down_sync(0xffffffffu, lv, o);
            int   oi = __shfl_down_sync(0xffffffffu, li, o);
            if (ov > lv || (ov == lv && oi < li)) { lv = ov; li = oi; }
        }
        if ((tid & 31) == 0) { redv[tid >> 5] = lv; redi[tid >> 5] = li; }
        __syncthreads();
        // ---- cross-warp reduce (exactly 32 warps) ----
        if (tid < 32) {
            lv = redv[tid]; li = redi[tid];
#pragma unroll
            for (int o = 16; o > 0; o >>= 1) {
                float ov = __shfl_down_sync(0xffffffffu, lv, o);
                int   oi = __shfl_down_sync(0xffffffffu, li, o);
                if (ov > lv || (ov == lv && oi < li)) { lv = ov; li = oi; }
            }
            if (tid == 0) { redv[32] = lv; redi[32] = li; }
        }
        __syncthreads();

        float bv = redv[32];
        int   bi = redi[32];
        if (bv <= 0.0f) break;   // all remaining scores are -1 -> rows are zeros

        float4 bbx = sbox[bi];
        float  bar = sarea[bi];
        int    ci  = scls[bi];

        if (tid == 0) {
            orow[t * 6 + 0] = bbx.x;
            orow[t * 6 + 1] = bbx.y;
            orow[t * 6 + 2] = bbx.z;
            orow[t * 6 + 3] = bbx.w;
            orow[t * 6 + 4] = bv;
            orow[t * 6 + 5] = (float)ci;
        }

        // ---- suppression: only same-class, not-yet-suppressed elements ----
        unsigned int cb = (unsigned int)ci * 0x01010101u;
        unsigned int m0 = __vcmpeq4(p0, cb);
        unsigned int m1 = __vcmpeq4(p1, cb);
        unsigned int m2 = __vcmpeq4(p2, cb);
        if (m0 | m1 | m2) {
#pragma unroll
            for (int k = 0; k < KPT; k++) {
                unsigned int mk = (k < 4) ? (m0 >> (8 * k))
                                : (k < 8) ? (m1 >> (8 * (k - 4)))
                                          : m2;
                if ((mk & 0xFFu) && s[k] > -1.0f) {
                    int e = k * NT + tid;
                    float4 bx = sbox[e];
                    float ix1 = fmaxf(bbx.x, bx.x);
                    float iy1 = fmaxf(bbx.y, bx.y);
                    float ix2 = fminf(bbx.z, bx.z);
                    float iy2 = fminf(bbx.w, bx.w);
                    float inter = fmaxf(ix2 - ix1, 0.0f) * fmaxf(iy2 - iy1, 0.0f);
                    float iou = inter / (bar + sarea[e] - inter);
                    if (iou > 0.45f) s[k] = -1.0f;
                }
            }
        }
    }

    // zero-fill remaining rows (d_out is poisoned, must write zeros)
    for (int i = t * 6 + tid; i < TOPK * 6; i += NT) orow[i] = 0.0f;
}

// ---------------------------------------------------------------------------
extern "C" void kernel_launch(void* const* d_in, const int* in_sizes, int n_in,
                              void* d_out, int out_size) {
    const float* loc   = (const float*)d_in[0];
    const float* conf  = (const float*)d_in[1];
    const float* prior = (const float*)d_in[2];
    float* out = (float*)d_out;

    cudaFuncSetAttribute(nms_kernel,
                         cudaFuncAttributeMaxDynamicSharedMemorySize,
                         SMEM_BYTES);

    preprocess_kernel<<<(NB * NP + 255) / 256, 256>>>(loc, conf, prior);
    nms_kernel<<<NB, NT, SMEM_BYTES>>>(out);
}

// round 2
// speedup vs baseline: 1.0713x; 1.0713x over previous
#include <cuda_runtime.h>
#include <cstdint>
#include <cfloat>

// Problem constants
#define NB   128
#define NP   8732
#define NC   21
#define TOPK 200

// NMS kernel config
#define NT   1024                 // threads per block (32 warps)
#define KPT  9                    // ceil(NP / NT)
#define NPAD (NT * KPT)           // 9216

// Scratch (device globals: no allocation allowed)
__device__ float         g_scores[NB * NP];
__device__ float4        g_boxes [NB * NP];
__device__ unsigned char g_cls   [NB * NP];

// ---------------------------------------------------------------------------
// Stage 1: softmax-max + class argmax + box decode, one thread per (b, p) row
// ---------------------------------------------------------------------------
__global__ void preprocess_kernel(const float* __restrict__ loc,
                                  const float* __restrict__ conf,
                                  const float* __restrict__ prior) {
    int row = blockIdx.x * blockDim.x + threadIdx.x;
    if (row >= NB * NP) return;

    const float* cp = conf + (size_t)row * NC;
    float c[NC];
#pragma unroll
    for (int i = 0; i < NC; i++) c[i] = cp[i];

    float m = c[0];
#pragma unroll
    for (int i = 1; i < NC; i++) m = fmaxf(m, c[i]);

    float sum = 0.0f;
#pragma unroll
    for (int i = 0; i < NC; i++) sum += expf(c[i] - m);

    // best non-background class (first max on ties, like jnp.argmax)
    float bm = c[1]; int bc = 1;
#pragma unroll
    for (int i = 2; i < NC; i++) {
        if (c[i] > bm) { bm = c[i]; bc = i; }
    }
    float score = expf(bm - m) / sum;
    float ms = (score > 0.01f) ? score : -1.0f;

    int p = row % NP;
    float4 l  = ((const float4*)loc)[row];
    float4 pr = ((const float4*)prior)[p];
    float cx = pr.x + l.x * 0.1f * pr.z;
    float cy = pr.y + l.y * 0.1f * pr.w;
    float w  = pr.z * expf(l.z * 0.2f);
    float h  = pr.w * expf(l.w * 0.2f);

    g_scores[row] = ms;
    g_boxes [row] = make_float4(cx - w * 0.5f, cy - h * 0.5f,
                                cx + w * 0.5f, cy + h * 0.5f);
    g_cls   [row] = (unsigned char)(bc - 1);
}

// ---------------------------------------------------------------------------
// 64-bit ordered key: (monotone float bits << 32) | ~index
// unsigned compare == (score desc, index asc) -> matches argmax first-tie
// ---------------------------------------------------------------------------
__device__ __forceinline__ unsigned long long pack_key(float v, int idx) {
    unsigned int b = __float_as_uint(v);
    b ^= (unsigned int)(((int)b >> 31) | 0x80000000);
    return ((unsigned long long)b << 32) | (unsigned int)(~idx);
}

// ---------------------------------------------------------------------------
// Stage 2: per-batch sequential NMS scan (one CTA per batch) with
// dirty-warp incremental argmax: a warp only recomputes its cached max key
// when one of its own scores changed (suppression is owner-local).
// ---------------------------------------------------------------------------
#define SMEM_BYTES (NPAD * 16 + NPAD * 4 + NPAD + 32 * 8 + 32 * 4 + 16)

__global__ __launch_bounds__(NT, 1)
void nms_kernel(float* __restrict__ out) {
    extern __shared__ unsigned char smem_raw[];
    float4*             sbox    = (float4*)smem_raw;              // NPAD float4
    float*              sarea   = (float*)(sbox + NPAD);          // NPAD floats
    unsigned char*      scls    = (unsigned char*)(sarea + NPAD); // NPAD bytes
    unsigned long long* warpkey = (unsigned long long*)(scls + NPAD); // 32 ull
    int*                sdirty  = (int*)(warpkey + 32);           // 32 ints
    unsigned long long* sbcast  = (unsigned long long*)(sdirty + 32);

    const int b    = blockIdx.x;
    const int tid  = threadIdx.x;
    const int wid  = tid >> 5;
    const int lane = tid & 31;
    const size_t base = (size_t)b * NP;

    float s[KPT];
    unsigned char myc[KPT];

#pragma unroll
    for (int k = 0; k < KPT; k++) {
        int e = k * NT + tid;
        if (e < NP) {
            float4 bx = g_boxes[base + e];
            sbox[e]  = bx;
            sarea[e] = (bx.z - bx.x) * (bx.w - bx.y);
            unsigned char cc = g_cls[base + e];
            scls[e] = cc;
            myc[k]  = cc;
            s[k]    = g_scores[base + e];
        } else {
            myc[k] = 0xFF;      // never matches a real class (0..19)
            s[k]   = -FLT_MAX;  // never selected
        }
    }
    // packed class bytes for fast same-class filtering (pad with 0xFF)
    unsigned int p0 = (unsigned int)myc[0] | ((unsigned int)myc[1] << 8) |
                      ((unsigned int)myc[2] << 16) | ((unsigned int)myc[3] << 24);
    unsigned int p1 = (unsigned int)myc[4] | ((unsigned int)myc[5] << 8) |
                      ((unsigned int)myc[6] << 16) | ((unsigned int)myc[7] << 24);
    unsigned int p2 = (unsigned int)myc[8] | 0xFFFFFF00u;

    if (lane == 0) sdirty[wid] = 1;
    __syncthreads();

    float* orow = out + (size_t)b * (TOPK * 6);

    int t = 0;
    for (; t < TOPK; t++) {
        // ---- dirty warps refresh their cached max key ----
        if (sdirty[wid]) {
            float lv = s[0]; int li = tid;
#pragma unroll
            for (int k = 1; k < KPT; k++) {
                if (s[k] > lv) { lv = s[k]; li = k * NT + tid; }
            }
            unsigned long long key = pack_key(lv, li);
#pragma unroll
            for (int o = 16; o > 0; o >>= 1) {
                unsigned long long ok = __shfl_down_sync(0xffffffffu, key, o);
                if (ok > key) key = ok;
            }
            if (lane == 0) { warpkey[wid] = key; sdirty[wid] = 0; }
        }
        __syncthreads();

        // ---- warp 0 reduces the 32 cached keys ----
        if (wid == 0) {
            unsigned long long key = warpkey[lane];
#pragma unroll
            for (int o = 16; o > 0; o >>= 1) {
                unsigned long long ok = __shfl_down_sync(0xffffffffu, key, o);
                if (ok > key) key = ok;
            }
            if (lane == 0) *sbcast = key;
        }
        __syncthreads();

        unsigned long long key = *sbcast;
        unsigned int hb = (unsigned int)(key >> 32);
        if (hb <= 0x80000000u) break;  // best score <= 0 -> rest are zero rows

        int bi = (int)(~(unsigned int)key);
        int ci = scls[bi];

        if (tid == 0) {
            float4 bbx = sbox[bi];
            unsigned int vb = (hb & 0x80000000u) ? (hb ^ 0x80000000u) : ~hb;
            orow[t * 6 + 0] = bbx.x;
            orow[t * 6 + 1] = bbx.y;
            orow[t * 6 + 2] = bbx.z;
            orow[t * 6 + 3] = bbx.w;
            orow[t * 6 + 4] = __uint_as_float(vb);
            orow[t * 6 + 5] = (float)ci;
        }

        // ---- suppression: only same-class, not-yet-suppressed elements ----
        unsigned int cb = (unsigned int)ci * 0x01010101u;
        unsigned int m0 = __vcmpeq4(p0, cb);
        unsigned int m1 = __vcmpeq4(p1, cb);
        unsigned int m2 = __vcmpeq4(p2, cb);
        if (m0 | m1 | m2) {
            float4 bbx = sbox[bi];
            float  bar = sarea[bi];
            bool changed = false;
#pragma unroll
            for (int k = 0; k < KPT; k++) {
                unsigned int mk = (k < 4) ? (m0 >> (8 * k))
                                : (k < 8) ? (m1 >> (8 * (k - 4)))
                                          : m2;
                if ((mk & 0xFFu) && s[k] > -1.0f) {
                    int e = k * NT + tid;
                    float4 bx = sbox[e];
                    float ix1 = fmaxf(bbx.x, bx.x);
                    float iy1 = fmaxf(bbx.y, bx.y);
                    float ix2 = fminf(bbx.z, bx.z);
                    float iy2 = fminf(bbx.w, bx.w);
                    float inter = fmaxf(ix2 - ix1, 0.0f) * fmaxf(iy2 - iy1, 0.0f);
                    float iou = inter / (bar + sarea[e] - inter);
                    if (iou > 0.45f) { s[k] = -1.0f; changed = true; }
                }
            }
            if (changed) sdirty[wid] = 1;  // warp-private flag, own warp only
        }
    }

    // zero-fill remaining rows (d_out is poisoned, must write zeros)
    for (int i = t * 6 + tid; i < TOPK * 6; i += NT) orow[i] = 0.0f;
}

// ---------------------------------------------------------------------------
extern "C" void kernel_launch(void* const* d_in, const int* in_sizes, int n_in,
                              void* d_out, int out_size) {
    const float* loc   = (const float*)d_in[0];
    const float* conf  = (const float*)d_in[1];
    const float* prior = (const float*)d_in[2];
    float* out = (float*)d_out;

    cudaFuncSetAttribute(nms_kernel,
                         cudaFuncAttributeMaxDynamicSharedMemorySize,
                         SMEM_BYTES);

    preprocess_kernel<<<(NB * NP + 255) / 256, 256>>>(loc, conf, prior);
    nms_kernel<<<NB, NT, SMEM_BYTES>>>(out);
}

// round 3
// speedup vs baseline: 1.2938x; 1.2077x over previous
#include <cuda_runtime.h>
#include <cstdint>
#include <cfloat>

// Problem constants
#define NB   128
#define NP   8732
#define NC   21
#define TOPK 200

// NMS kernel config
#define NT   1024                 // threads per block (32 warps)
#define KPT  9                    // ceil(NP / NT)
#define NPAD (NT * KPT)           // 9216
#define WELEM (KPT * 32)          // 288 sorted positions per warp

// Scratch (device globals: no allocation allowed)
__device__ float         g_scores[NB * NP];
__device__ float4        g_boxes [NB * NP];
__device__ unsigned char g_cls   [NB * NP];

// ---------------------------------------------------------------------------
// Stage 1: softmax-max + class argmax + box decode, one thread per (b, p) row
// ---------------------------------------------------------------------------
__global__ void preprocess_kernel(const float* __restrict__ loc,
                                  const float* __restrict__ conf,
                                  const float* __restrict__ prior) {
    int row = blockIdx.x * blockDim.x + threadIdx.x;
    if (row >= NB * NP) return;

    const float* cp = conf + (size_t)row * NC;
    float c[NC];
#pragma unroll
    for (int i = 0; i < NC; i++) c[i] = cp[i];

    float m = c[0];
#pragma unroll
    for (int i = 1; i < NC; i++) m = fmaxf(m, c[i]);

    float sum = 0.0f;
#pragma unroll
    for (int i = 0; i < NC; i++) sum += expf(c[i] - m);

    float bm = c[1]; int bc = 1;
#pragma unroll
    for (int i = 2; i < NC; i++) {
        if (c[i] > bm) { bm = c[i]; bc = i; }
    }
    float score = expf(bm - m) / sum;
    float ms = (score > 0.01f) ? score : -1.0f;

    int p = row % NP;
    float4 l  = ((const float4*)loc)[row];
    float4 pr = ((const float4*)prior)[p];
    float cx = pr.x + l.x * 0.1f * pr.z;
    float cy = pr.y + l.y * 0.1f * pr.w;
    float w  = pr.z * expf(l.z * 0.2f);
    float h  = pr.w * expf(l.w * 0.2f);

    g_scores[row] = ms;
    g_boxes [row] = make_float4(cx - w * 0.5f, cy - h * 0.5f,
                                cx + w * 0.5f, cy + h * 0.5f);
    g_cls   [row] = (unsigned char)(bc - 1);
}

// ---------------------------------------------------------------------------
// 64-bit key: [monotone score bits : 32][~orig_idx : 16][sorted pos : 16]
// unsigned MAX == (score desc, orig_idx asc). pos rides along for free.
// ---------------------------------------------------------------------------
__device__ __forceinline__ unsigned long long
pack_key(float v, unsigned int oidx, unsigned int pos) {
    unsigned int b = __float_as_uint(v);
    b ^= (unsigned int)(((int)b >> 31) | 0x80000000);
    return ((unsigned long long)b << 32) |
           ((unsigned long long)((~oidx) & 0xFFFFu) << 16) |
           (unsigned long long)pos;
}

// ---------------------------------------------------------------------------
// Stage 2: one CTA per batch. Elements counting-sorted by class so each warp
// holds a contiguous class range -> suppression touches ~2 warps/iter.
// Dirty-warp incremental argmax, single barrier per iteration.
// ---------------------------------------------------------------------------
// smem: sbox NPAD*16 | sscore NPAD*4 | clsidx NPAD*4 | warpkey 32*8 | hist 32*4
#define SMEM_BYTES (NPAD * 16 + NPAD * 4 + NPAD * 4 + 32 * 8 + 32 * 4 + 64)

__global__ __launch_bounds__(NT, 1)
void nms_kernel(float* __restrict__ out) {
    extern __shared__ unsigned char smem_raw[];
    float4*             sbox    = (float4*)smem_raw;                   // NPAD
    float*              sscore  = (float*)(sbox + NPAD);               // NPAD
    unsigned int*       clsidx  = (unsigned int*)(sscore + NPAD);      // NPAD
    unsigned long long* warpkey = (unsigned long long*)(clsidx + NPAD);// 32
    int*                hist    = (int*)(warpkey + 32);                // 32

    const int b    = blockIdx.x;
    const int tid  = threadIdx.x;
    const int wid  = tid >> 5;
    const int lane = tid & 31;
    const size_t base = (size_t)b * NP;
    const unsigned int full = 0xffffffffu;

    // ---- counting sort by class ----
    if (tid < 32) hist[tid] = 0;
    __syncthreads();

    unsigned char oc[KPT];
#pragma unroll
    for (int i = 0; i < KPT; i++) {
        int e = tid + i * NT;
        if (e < NP) {
            oc[i] = g_cls[base + e];
            atomicAdd(&hist[oc[i]], 1);
        }
    }
    __syncthreads();
    if (tid == 0) {
        int run = 0;
#pragma unroll
        for (int c = 0; c < NC - 1; c++) { int t = hist[c]; hist[c] = run; run += t; }
    }
    __syncthreads();
#pragma unroll
    for (int i = 0; i < KPT; i++) {
        int e = tid + i * NT;
        if (e < NP) {
            int c = oc[i];
            int pos = atomicAdd(&hist[c], 1);
            sbox[pos]   = g_boxes[base + e];
            sscore[pos] = g_scores[base + e];
            clsidx[pos] = ((unsigned int)c << 16) | (unsigned int)e;
        }
    }
    // pad tail
    for (int p = NP + tid; p < NPAD; p += NT) {
        clsidx[p] = 0xFFu << 16;
        sscore[p] = -FLT_MAX;
    }
    __syncthreads();

    // ---- load my sorted elements into registers ----
    float s[KPT];
    unsigned char myc[KPT];
    const int wbase = wid * WELEM;
#pragma unroll
    for (int k = 0; k < KPT; k++) {
        int e = wbase + (k << 5) + lane;
        s[k]   = sscore[e];
        myc[k] = (unsigned char)(clsidx[e] >> 16);
    }
    unsigned int p0 = (unsigned int)myc[0] | ((unsigned int)myc[1] << 8) |
                      ((unsigned int)myc[2] << 16) | ((unsigned int)myc[3] << 24);
    unsigned int p1 = (unsigned int)myc[4] | ((unsigned int)myc[5] << 8) |
                      ((unsigned int)myc[6] << 16) | ((unsigned int)myc[7] << 24);
    unsigned int p2 = (unsigned int)myc[8] | 0xFFFFFF00u;
    int clo = __shfl_sync(full, (int)myc[0], 0);    // class at first warp pos
    int chi = __shfl_sync(full, (int)myc[8], 31);   // class at last warp pos

    bool dirty = true;
    float* orow = out + (size_t)b * (TOPK * 6);

    int t = 0;
    for (; t < TOPK; t++) {
        // ---- dirty warps refresh their cached max key ----
        if (dirty) {
            unsigned long long key = 0;
#pragma unroll
            for (int k = 0; k < KPT; k++) {
                int e = wbase + (k << 5) + lane;
                unsigned long long kk =
                    pack_key(s[k], clsidx[e] & 0xFFFFu, (unsigned int)e);
                if (kk > key) key = kk;
            }
#pragma unroll
            for (int o = 16; o > 0; o >>= 1) {
                unsigned long long ok = __shfl_xor_sync(full, key, o);
                if (ok > key) key = ok;
            }
            if (lane == 0) warpkey[wid] = key;
            dirty = false;
        }
        __syncthreads();

        // ---- all warps redundantly reduce the 32 cached keys ----
        unsigned long long key = warpkey[lane];
#pragma unroll
        for (int o = 16; o > 0; o >>= 1) {
            unsigned long long ok = __shfl_xor_sync(full, key, o);
            if (ok > key) key = ok;
        }

        unsigned int hb = (unsigned int)(key >> 32);
        if (hb <= 0x80000000u) break;       // best score <= 0 -> zero rows

        int pos = (int)(key & 0xFFFFu);
        int ci  = (int)(clsidx[pos] >> 16); // broadcast LDS

        if (tid == 0) {
            float4 bbx = sbox[pos];
            orow[t * 6 + 0] = bbx.x;
            orow[t * 6 + 1] = bbx.y;
            orow[t * 6 + 2] = bbx.z;
            orow[t * 6 + 3] = bbx.w;
            orow[t * 6 + 4] = __uint_as_float(hb ^ 0x80000000u);
            orow[t * 6 + 5] = (float)ci;
        }

        // ---- suppression: only warps whose class range contains ci ----
        if (ci >= clo && ci <= chi) {
            float4 bbx = sbox[pos];                    // broadcast LDS.128
            float  bar = (bbx.z - bbx.x) * (bbx.w - bbx.y);
            unsigned int cb = (unsigned int)ci * 0x01010101u;
            unsigned int m0 = __vcmpeq4(p0, cb);
            unsigned int m1 = __vcmpeq4(p1, cb);
            unsigned int m2 = __vcmpeq4(p2, cb);
            bool changed = false;
#pragma unroll
            for (int k = 0; k < KPT; k++) {
                unsigned int mk = (k < 4) ? (m0 >> (8 * k))
                                : (k < 8) ? (m1 >> (8 * (k - 4)))
                                          : m2;
                if ((mk & 0xFFu) && s[k] > -1.0f) {
                    int e = wbase + (k << 5) + lane;
                    float4 bx = sbox[e];
                    float ix1 = fmaxf(bbx.x, bx.x);
                    float iy1 = fmaxf(bbx.y, bx.y);
                    float ix2 = fminf(bbx.z, bx.z);
                    float iy2 = fminf(bbx.w, bx.w);
                    float inter = fmaxf(ix2 - ix1, 0.0f) * fmaxf(iy2 - iy1, 0.0f);
                    float ar = (bx.z - bx.x) * (bx.w - bx.y);
                    float iou = inter / (bar + ar - inter);
                    if (iou > 0.45f) { s[k] = -1.0f; changed = true; }
                }
            }
            dirty = dirty | __any_sync(full, changed);
        }
    }

    // zero-fill remaining rows (d_out is poisoned, must write zeros)
    for (int i = t * 6 + tid; i < TOPK * 6; i += NT) orow[i] = 0.0f;
}

// ---------------------------------------------------------------------------
extern "C" void kernel_launch(void* const* d_in, const int* in_sizes, int n_in,
                              void* d_out, int out_size) {
    const float* loc   = (const float*)d_in[0];
    const float* conf  = (const float*)d_in[1];
    const float* prior = (const float*)d_in[2];
    float* out = (float*)d_out;

    cudaFuncSetAttribute(nms_kernel,
                         cudaFuncAttributeMaxDynamicSharedMemorySize,
                         SMEM_BYTES);

    preprocess_kernel<<<(NB * NP + 255) / 256, 256>>>(loc, conf, prior);
    nms_kernel<<<NB, NT, SMEM_BYTES>>>(out);
}